// round 17
// baseline (speedup 1.0000x reference)
#include <cuda_runtime.h>
#include <cuda_bf16.h>
#include <cstdint>

#define N_NODES 100000
#define N_EDGES 800000
#define D_IN    256
#define D_OUT   128

#define M_TILE  128
#define TILES   782              // ceil(100000 / 128)
#define GRID_P  148
#define THREADS 512
#define SCAT_BLOCKS 12500        // N_EDGES*16/4/256 (4 edges per thread)

// Aggregation buffer: [N_NODES][128] = [agg_a(0:64) | agg_b(64:128)].
// BSS-zeroed at load; gemm re-zeroes each tile after consuming it.
__device__ __align__(16) float g_x[(size_t)N_NODES * 128];

// W^T tf32 image: [n=128][k=256], XOR-swizzled: word n*256 + (k ^ ((n&7)<<2))
__device__ __align__(16) uint32_t g_wt[128 * 256];

__device__ __forceinline__ uint32_t f2tf32(float f) {
    uint32_t u;
    asm("cvt.rna.tf32.f32 %0, %1;" : "=r"(u) : "f"(f));
    return u;
}

// ---------------------------------------------------------------------------
// Kernel 1: scatter-add, 4 edges x 2 types per thread (MLP=8) + W prep blocks.
// Edge reads: evict_first; atomics: evict_last (g_x stays L2-resident).
// ---------------------------------------------------------------------------
__global__ void scatter_prep_kernel(const float* __restrict__ edata_a,
                                    const int* __restrict__ recv_a,
                                    const float* __restrict__ edata_b,
                                    const int* __restrict__ recv_b,
                                    const float* __restrict__ W) {
    if (blockIdx.x >= SCAT_BLOCKS) {
        int idx = (blockIdx.x - SCAT_BLOCKS) * 256 + threadIdx.x;
        if (idx < D_IN * D_OUT) {
            int n = idx & 127;
            int k = idx >> 7;
            g_wt[n * 256 + (k ^ ((n & 7) << 2))] = f2tf32(W[k * D_OUT + n]);
        }
        return;
    }
    int idx = blockIdx.x * 256 + threadIdx.x;      // 0 .. 3.2M-1
    int q   = idx & 15;
    int e0  = (idx >> 4) * 4;

    uint64_t pol_ef, pol_el;
    asm("createpolicy.fractional.L2::evict_first.b64 %0, 1.0;" : "=l"(pol_ef));
    asm("createpolicy.fractional.L2::evict_last.b64 %0, 1.0;"  : "=l"(pol_el));

    float4 va[4], vb[4];
    #pragma unroll
    for (int i = 0; i < 4; i++) {
        const float4* pa = reinterpret_cast<const float4*>(edata_a) + (size_t)(e0 + i) * 16 + q;
        asm volatile("ld.global.nc.L2::cache_hint.v4.f32 {%0,%1,%2,%3}, [%4], %5;"
                     : "=f"(va[i].x), "=f"(va[i].y), "=f"(va[i].z), "=f"(va[i].w)
                     : "l"(pa), "l"(pol_ef));
    }
    #pragma unroll
    for (int i = 0; i < 4; i++) {
        const float4* pb = reinterpret_cast<const float4*>(edata_b) + (size_t)(e0 + i) * 16 + q;
        asm volatile("ld.global.nc.L2::cache_hint.v4.f32 {%0,%1,%2,%3}, [%4], %5;"
                     : "=f"(vb[i].x), "=f"(vb[i].y), "=f"(vb[i].z), "=f"(vb[i].w)
                     : "l"(pb), "l"(pol_ef));
    }

    int4 ra = *reinterpret_cast<const int4*>(recv_a + e0);
    int4 rb = *reinterpret_cast<const int4*>(recv_b + e0);
    int ras[4] = {ra.x, ra.y, ra.z, ra.w};
    int rbs[4] = {rb.x, rb.y, rb.z, rb.w};

    #pragma unroll
    for (int i = 0; i < 4; i++) {
        float* da = g_x + (size_t)ras[i] * 128 + q * 4;
        asm volatile("red.global.L2::cache_hint.add.v4.f32 [%0], {%1,%2,%3,%4}, %5;"
                     :: "l"(da), "f"(va[i].x), "f"(va[i].y), "f"(va[i].z), "f"(va[i].w),
                        "l"(pol_el) : "memory");
    }
    #pragma unroll
    for (int i = 0; i < 4; i++) {
        float* db = g_x + (size_t)rbs[i] * 128 + 64 + q * 4;
        asm volatile("red.global.L2::cache_hint.add.v4.f32 [%0], {%1,%2,%3,%4}, %5;"
                     :: "l"(db), "f"(vb[i].x), "f"(vb[i].y), "f"(vb[i].z), "f"(vb[i].w),
                        "l"(pol_el) : "memory");
    }
}

// ---------------------------------------------------------------------------
__device__ __forceinline__ void mma_tf32(float* d, uint32_t a0, uint32_t a1,
                                         uint32_t a2, uint32_t a3,
                                         uint32_t b0, uint32_t b1) {
    asm volatile(
        "mma.sync.aligned.m16n8k8.row.col.f32.tf32.tf32.f32 "
        "{%0,%1,%2,%3}, {%4,%5,%6,%7}, {%8,%9}, {%0,%1,%2,%3};"
        : "+f"(d[0]), "+f"(d[1]), "+f"(d[2]), "+f"(d[3])
        : "r"(a0), "r"(a1), "r"(a2), "r"(a3), "r"(b0), "r"(b1));
}

// SMEM (words): sW [0, 32768), sX0 [32768, 40960), sX1 [40960, 49152)
// X chunk buffer: 128 rows x 64 words (k=64) = 8192 words = 32KB
#define SW_BASE 0
#define SX0     32768
#define SX1     40960
#define SMEM_WORDS 49152       // 196608 bytes

// ---------------------------------------------------------------------------
// Kernel 2: persistent TF32 HMMA GEMM, quarter-K (64-k) ping-pong buffers.
// 512 threads / 16 warps (4 per SMSP), M_TILE=128, warp grid 4Mx4N,
// warp tile 32x32, XOR swizzle. Chunks 0,1 from g_x; 2,3 from vdata.
// ---------------------------------------------------------------------------
__global__ __launch_bounds__(THREADS, 1)
void gemm_mma_kernel(const float* __restrict__ vdata,
                     const float* __restrict__ bias,
                     float* __restrict__ out) {
    extern __shared__ uint32_t smem[];
    const uint32_t smem_u32 = (uint32_t)__cvta_generic_to_shared(smem);
    const int tid  = threadIdx.x;
    const int wid  = tid >> 5;
    const int lane = tid & 31;
    const int grp  = lane >> 2;
    const int qp   = lane & 3;
    const int xg   = grp << 2;        // per-thread swizzle XOR

    const int m0 = (wid & 3) * 32;    // warp M band (of 128)
    const int n0 = (wid >> 2) * 32;   // warp N quarter (of 128)

    // ---- Stage W^T swizzled image once (8192 uint4) ----
    {
        const uint4* src = reinterpret_cast<const uint4*>(g_wt);
        uint4* dst = reinterpret_cast<uint4*>(smem + SW_BASE);
        #pragma unroll
        for (int i = 0; i < 16; i++) dst[i * THREADS + tid] = src[i * THREADS + tid];
    }

    float2 bv[4];
    #pragma unroll
    for (int j = 0; j < 4; j++)
        bv[j] = *reinterpret_cast<const float2*>(bias + n0 + j * 8 + qp * 2);

    const float4* A4 = reinterpret_cast<const float4*>(g_x);
    const float4* V4 = reinterpret_cast<const float4*>(vdata);

    // per-thread staging geometry: 4 float4 per chunk
    int rr[4], cw[4];
    uint32_t soff[4];        // word offset within chunk buffer
    #pragma unroll
    for (int i = 0; i < 4; i++) {
        int j = i * THREADS + tid;       // 0..2047
        int r = j >> 4, c = j & 15;      // row 0..127, f4-in-chunk 0..15
        rr[i] = r; cw[i] = c;
        soff[i] = (uint32_t)(r * 64 + ((c * 4) ^ ((r & 7) << 2)));
    }

    // issue chunk c (0..3) of tile t into buffer (c&1)
    auto issue_chunk = [&](int t, int c) {
        if (t < TILES) {
            int node0 = t * M_TILE;
            uint32_t base = smem_u32 + (uint32_t)((c & 1) ? SX1 : SX0) * 4u;
            const float4* S = (c < 2) ? A4 : V4;
            int fc = (c & 1) ? 16 : 0;   // f4 col base within its source half
            #pragma unroll
            for (int i = 0; i < 4; i++) {
                int node = node0 + rr[i];
                unsigned ssz = (node < N_NODES) ? 16u : 0u;
                const float4* s = S + (size_t)node * 32 + fc + cw[i];
                asm volatile("cp.async.cg.shared.global [%0], [%1], 16, %2;"
                             :: "r"(base + soff[i] * 4u), "l"(s), "r"(ssz) : "memory");
            }
        }
        asm volatile("cp.async.commit_group;" ::: "memory");  // empty group OK
    };

    // compute chunk c (k = 64c .. 64c+63) from its buffer into acc
    auto compute_chunk = [&](float acc[2][4][4], int c) {
        const int xb = (c & 1) ? SX1 : SX0;
        #pragma unroll 4
        for (int ks = 0; ks < 8; ks++) {
            int ox  = ((ks * 8) ^ xg) + qp;          // col in X chunk (0..63)
            int ox4 = ox ^ 4;
            int ow  = (((c * 8 + ks) * 8) ^ xg) + qp; // col in W row (0..255)
            int ow4 = ow ^ 4;
            uint32_t a[2][4];
            #pragma unroll
            for (int mb = 0; mb < 2; mb++) {
                int base = xb + (m0 + mb * 16 + grp) * 64;
                a[mb][0] = smem[base + ox];
                a[mb][1] = smem[base + 8 * 64 + ox];
                a[mb][2] = smem[base + ox4];
                a[mb][3] = smem[base + 8 * 64 + ox4];
            }
            #pragma unroll
            for (int j = 0; j < 4; j++) {
                int baseB = SW_BASE + (n0 + j * 8 + grp) * 256;
                uint32_t b0 = smem[baseB + ow];
                uint32_t b1 = smem[baseB + ow4];
                mma_tf32(acc[0][j], a[0][0], a[0][1], a[0][2], a[0][3], b0, b1);
                mma_tf32(acc[1][j], a[1][0], a[1][1], a[1][2], a[1][3], b0, b1);
            }
        }
    };

    int t = blockIdx.x;
    if (t < TILES) { issue_chunk(t, 0); issue_chunk(t, 1); }

    while (t < TILES) {
        const int node0 = t * M_TILE;
        const int tn = t + GRID_P;

        float acc[2][4][4];
        #pragma unroll
        for (int mb = 0; mb < 2; mb++)
            #pragma unroll
            for (int j = 0; j < 4; j++)
                #pragma unroll
                for (int c = 0; c < 4; c++) acc[mb][j][c] = 0.f;

        // chunk 0 (g_x k 0:64)
        asm volatile("cp.async.wait_group 1;" ::: "memory");
        __syncthreads();
        compute_chunk(acc, 0);
        __syncthreads();
        issue_chunk(t, 2);

        // chunk 1 (g_x k 64:128)
        asm volatile("cp.async.wait_group 1;" ::: "memory");
        __syncthreads();
        compute_chunk(acc, 1);
        __syncthreads();
        issue_chunk(t, 3);

        // chunk 2 (vdata k 0:64) — g_x copies all complete; zero consumed rows
        asm volatile("cp.async.wait_group 1;" ::: "memory");
        __syncthreads();
        {
            #pragma unroll
            for (int i = 0; i < 8; i++) {
                int j = i * THREADS + tid;       // 0..4095
                int r = j >> 5, c4 = j & 31;
                int node = node0 + r;
                if (node < N_NODES)
                    reinterpret_cast<float4*>(g_x)[(size_t)node * 32 + c4] =
                        make_float4(0.f, 0.f, 0.f, 0.f);
            }
        }
        compute_chunk(acc, 2);
        __syncthreads();
        issue_chunk(tn, 0);

        // chunk 3 (vdata k 64:128)
        asm volatile("cp.async.wait_group 1;" ::: "memory");
        __syncthreads();
        compute_chunk(acc, 3);
        __syncthreads();
        issue_chunk(tn, 1);

        // ---- epilogue ----
        #pragma unroll
        for (int mb = 0; mb < 2; mb++) {
            int row_a = node0 + m0 + mb * 16 + grp;
            int row_b = row_a + 8;
            #pragma unroll
            for (int j = 0; j < 4; j++) {
                int col = n0 + j * 8 + qp * 2;
                if (row_a < N_NODES) {
                    float2 o = make_float2(acc[mb][j][0] + bv[j].x,
                                           acc[mb][j][1] + bv[j].y);
                    *reinterpret_cast<float2*>(out + (size_t)row_a * D_OUT + col) = o;
                }
                if (row_b < N_NODES) {
                    float2 o = make_float2(acc[mb][j][2] + bv[j].x,
                                           acc[mb][j][3] + bv[j].y);
                    *reinterpret_cast<float2*>(out + (size_t)row_b * D_OUT + col) = o;
                }
            }
        }
        t = tn;
    }
}

// ---------------------------------------------------------------------------
extern "C" void kernel_launch(void* const* d_in, const int* in_sizes, int n_in,
                              void* d_out, int out_size) {
    const float* vdata   = (const float*)d_in[0];
    const float* edata_a = (const float*)d_in[1];
    const float* edata_b = (const float*)d_in[2];
    const int*   conn_a  = (const int*)d_in[3];
    const int*   conn_b  = (const int*)d_in[4];
    const float* W       = (const float*)d_in[5];
    const float* bias    = (const float*)d_in[6];
    float*       out     = (float*)d_out;

    scatter_prep_kernel<<<SCAT_BLOCKS + 128, 256>>>(
        edata_a, conn_a + N_EDGES, edata_b, conn_b + N_EDGES, W);

    {
        size_t smem_bytes = SMEM_WORDS * sizeof(uint32_t);   // 196608
        cudaFuncSetAttribute(gemm_mma_kernel,
                             cudaFuncAttributeMaxDynamicSharedMemorySize,
                             (int)smem_bytes);
        gemm_mma_kernel<<<GRID_P, THREADS, smem_bytes>>>(vdata, bias, out);
    }
}